// round 1
// baseline (speedup 1.0000x reference)
#include <cuda_runtime.h>
#include <math.h>

#define Bq 16
#define Tq 1024
#define Dq 512
#define Hq 8
#define HD 64
#define FFN 2048
#define SEH 256
#define NTOK (Bq*Tq)   // 16384

// ---------------- scratch (device globals; no allocs allowed) ----------------
__device__ float g_y[NTOK];              // row means (B,T)
__device__ float g_z[Bq*SEH];            // relu(y@se_w1)
__device__ float g_gate[NTOK];           // sigmoid gate
__device__ float g_x1[(size_t)NTOK*Dq];  // x after SE gate
__device__ float g_n[(size_t)NTOK*Dq];   // LN1 out
__device__ float g_q[(size_t)NTOK*Dq];
__device__ float g_k[(size_t)NTOK*Dq];
__device__ float g_v[(size_t)NTOK*Dq];
__device__ float g_x2[(size_t)NTOK*Dq];  // x1 + attn
__device__ float g_n2[(size_t)NTOK*Dq];  // LN2 out
__device__ float g_h[(size_t)NTOK*FFN];  // gelu(ffn1)

// ---------------- SE: row mean over D ----------------
__global__ void row_mean_kernel(const float* __restrict__ x) {
    int warp = blockIdx.x * (blockDim.x >> 5) + (threadIdx.x >> 5);
    int lane = threadIdx.x & 31;
    if (warp >= NTOK) return;
    const float4* row = (const float4*)(x + (size_t)warp * Dq);
    float s = 0.f;
    #pragma unroll
    for (int it = 0; it < 4; it++) {
        float4 v = row[lane + it * 32];
        s += v.x + v.y + v.z + v.w;
    }
    #pragma unroll
    for (int o = 16; o; o >>= 1) s += __shfl_xor_sync(0xffffffffu, s, o);
    if (lane == 0) g_y[warp] = s * (1.0f / Dq);
}

// z = relu(y @ se_w1) : (16,1024)@(1024,256)
__global__ void se1_kernel(const float* __restrict__ se_w1) {
    __shared__ float ys[Tq];
    int b = blockIdx.x;
    for (int i = threadIdx.x; i < Tq; i += 256) ys[i] = g_y[b * Tq + i];
    __syncthreads();
    int j = threadIdx.x;  // 256 threads
    float acc = 0.f;
    #pragma unroll 8
    for (int t = 0; t < Tq; t++) acc = fmaf(ys[t], se_w1[t * SEH + j], acc);
    g_z[b * SEH + j] = fmaxf(acc, 0.f);
}

// gate = sigmoid(z @ se_w2) : (16,256)@(256,1024)
__global__ void se2_kernel(const float* __restrict__ se_w2) {
    __shared__ float zs[SEH];
    int b = blockIdx.x;
    if (threadIdx.x < SEH) zs[threadIdx.x] = g_z[b * SEH + threadIdx.x];
    __syncthreads();
    int t = threadIdx.x;  // 1024 threads
    float acc = 0.f;
    #pragma unroll 8
    for (int j = 0; j < SEH; j++) acc = fmaf(zs[j], se_w2[j * Tq + t], acc);
    g_gate[b * Tq + t] = 1.0f / (1.0f + expf(-acc));
}

// ---------------- block reduce (128 threads) ----------------
__device__ __forceinline__ float block_reduce_sum128(float v, float* red) {
    #pragma unroll
    for (int o = 16; o; o >>= 1) v += __shfl_xor_sync(0xffffffffu, v, o);
    int w = threadIdx.x >> 5;
    if ((threadIdx.x & 31) == 0) red[w] = v;
    __syncthreads();
    float r = red[0] + red[1] + red[2] + red[3];
    __syncthreads();
    return r;
}

// x1 = x*(1+gate); n = LN(x1)*g + b     (one block per token row, 128 thr)
__global__ void se_ln1_kernel(const float* __restrict__ x,
                              const float* __restrict__ gam,
                              const float* __restrict__ bet) {
    __shared__ float red[4];
    int row = blockIdx.x;
    float gm = 1.0f + g_gate[row];
    float4 v = ((const float4*)(x + (size_t)row * Dq))[threadIdx.x];
    v.x *= gm; v.y *= gm; v.z *= gm; v.w *= gm;
    ((float4*)(g_x1 + (size_t)row * Dq))[threadIdx.x] = v;
    float s = block_reduce_sum128(v.x + v.y + v.z + v.w, red);
    float mu = s * (1.0f / Dq);
    float d0 = v.x - mu, d1 = v.y - mu, d2 = v.z - mu, d3 = v.w - mu;
    float ss = block_reduce_sum128(d0*d0 + d1*d1 + d2*d2 + d3*d3, red);
    float rstd = rsqrtf(ss * (1.0f / Dq) + 1e-5f);
    float4 gg = ((const float4*)gam)[threadIdx.x];
    float4 bb = ((const float4*)bet)[threadIdx.x];
    float4 o = make_float4(d0*rstd*gg.x + bb.x, d1*rstd*gg.y + bb.y,
                           d2*rstd*gg.z + bb.z, d3*rstd*gg.w + bb.w);
    ((float4*)(g_n + (size_t)row * Dq))[threadIdx.x] = o;
}

// n2 = LN(x2)*g + b
__global__ void ln2_kernel(const float* __restrict__ gam,
                           const float* __restrict__ bet) {
    __shared__ float red[4];
    int row = blockIdx.x;
    float4 v = ((const float4*)(g_x2 + (size_t)row * Dq))[threadIdx.x];
    float s = block_reduce_sum128(v.x + v.y + v.z + v.w, red);
    float mu = s * (1.0f / Dq);
    float d0 = v.x - mu, d1 = v.y - mu, d2 = v.z - mu, d3 = v.w - mu;
    float ss = block_reduce_sum128(d0*d0 + d1*d1 + d2*d2 + d3*d3, red);
    float rstd = rsqrtf(ss * (1.0f / Dq) + 1e-5f);
    float4 gg = ((const float4*)gam)[threadIdx.x];
    float4 bb = ((const float4*)bet)[threadIdx.x];
    float4 o = make_float4(d0*rstd*gg.x + bb.x, d1*rstd*gg.y + bb.y,
                           d2*rstd*gg.z + bb.z, d3*rstd*gg.w + bb.w);
    ((float4*)(g_n2 + (size_t)row * Dq))[threadIdx.x] = o;
}

// ---------------- SGEMM 128x128x8, 256 thr, 8x8 micro-tiles ----------------
// MODE 0: C = A@B        MODE 1: C = gelu(A@B + bias)   MODE 2: C = resid + A@B + bias
template <int MODE>
__global__ __launch_bounds__(256)
void sgemm_kernel(const float* __restrict__ A, const float* __restrict__ B,
                  float* __restrict__ C, int M, int N, int K,
                  const float* __restrict__ bias, const float* __restrict__ resid) {
    __shared__ float As[8][128];
    __shared__ float Bs[8][128];
    const int tid = threadIdx.x;
    const int brow = blockIdx.y * 128;
    const int bcol = blockIdx.x * 128;
    const int tr = tid >> 4;          // 0..15
    const int tc = tid & 15;          // 0..15
    const int aRow = tid >> 1;        // 0..127
    const int aCol = (tid & 1) * 4;   // 0 or 4
    const int bRow = tid >> 5;        // 0..7
    const int bCol = (tid & 31) * 4;  // 0..124

    const float* Aptr = A + (size_t)(brow + aRow) * K + aCol;
    const float* Bptr = B + (size_t)bRow * N + bcol + bCol;

    float acc[8][8];
    #pragma unroll
    for (int i = 0; i < 8; i++)
        #pragma unroll
        for (int j = 0; j < 8; j++) acc[i][j] = 0.f;

    for (int k0 = 0; k0 < K; k0 += 8) {
        float4 a4 = *(const float4*)Aptr;  Aptr += 8;
        float4 b4 = *(const float4*)Bptr;  Bptr += (size_t)8 * N;
        As[aCol + 0][aRow] = a4.x;
        As[aCol + 1][aRow] = a4.y;
        As[aCol + 2][aRow] = a4.z;
        As[aCol + 3][aRow] = a4.w;
        *(float4*)&Bs[bRow][bCol] = b4;
        __syncthreads();
        #pragma unroll
        for (int kk = 0; kk < 8; kk++) {
            float ar[8], br[8];
            #pragma unroll
            for (int i = 0; i < 8; i++) ar[i] = As[kk][tr * 8 + i];
            #pragma unroll
            for (int j = 0; j < 8; j++) br[j] = Bs[kk][tc * 8 + j];
            #pragma unroll
            for (int i = 0; i < 8; i++)
                #pragma unroll
                for (int j = 0; j < 8; j++)
                    acc[i][j] = fmaf(ar[i], br[j], acc[i][j]);
        }
        __syncthreads();
    }

    #pragma unroll
    for (int i = 0; i < 8; i++) {
        size_t row = (size_t)(brow + tr * 8 + i);
        #pragma unroll
        for (int j0 = 0; j0 < 8; j0 += 4) {
            int col0 = bcol + tc * 8 + j0;
            float4 o;
            float vv[4];
            #pragma unroll
            for (int j = 0; j < 4; j++) {
                float a = acc[i][j0 + j];
                if (MODE == 1) {
                    float u = a + bias[col0 + j];
                    a = 0.5f * u * (1.0f + erff(u * 0.70710678118654752f));
                } else if (MODE == 2) {
                    a = a + bias[col0 + j] + resid[row * N + col0 + j];
                }
                vv[j] = a;
            }
            o.x = vv[0]; o.y = vv[1]; o.z = vv[2]; o.w = vv[3];
            *(float4*)&C[row * N + col0] = o;
        }
    }
}

// ---------------- flash attention: 64q x 64k tiles, head dim 64 ----------------
// grid (T/64, H, B), 256 threads. x2 = x1 + softmax(QK^T/sqrt(d)) V
#define FA_PAD 68
#define FA_SMEM (3 * 64 * FA_PAD * 4)
__global__ __launch_bounds__(256)
void flash_kernel() {
    extern __shared__ float sm[];
    float* Qt = sm;                  // [dd][q]   64 x 68
    float* Kt = sm + 64 * FA_PAD;    // [dd][k] ; reused as Pt[k][q]
    float* Vs = Kt + 64 * FA_PAD;    // [key][dd]

    const int tid = threadIdx.x;
    const int qblk = blockIdx.x;
    const int h = blockIdx.y;
    const int b = blockIdx.z;
    const int tr = tid >> 4;   // q group 0..15
    const int tc = tid & 15;   // col group 0..15
    const size_t base = ((size_t)b * Tq) * Dq + h * HD;
    const float scale = 0.125f;  // 1/sqrt(64)

    // load Q tile transposed + prescaled
    #pragma unroll
    for (int it = 0; it < 4; it++) {
        int idx = tid + it * 256;       // float4 index 0..1023
        int qr = idx >> 4;              // 0..63
        int d4 = (idx & 15) * 4;
        float4 v = *(const float4*)(g_q + base + (size_t)(qblk * 64 + qr) * Dq + d4);
        Qt[(d4 + 0) * FA_PAD + qr] = v.x * scale;
        Qt[(d4 + 1) * FA_PAD + qr] = v.y * scale;
        Qt[(d4 + 2) * FA_PAD + qr] = v.z * scale;
        Qt[(d4 + 3) * FA_PAD + qr] = v.w * scale;
    }

    float m_i[4], l_i[4], o_[4][4];
    #pragma unroll
    for (int i = 0; i < 4; i++) {
        m_i[i] = -INFINITY; l_i[i] = 0.f;
        #pragma unroll
        for (int j = 0; j < 4; j++) o_[i][j] = 0.f;
    }

    for (int kt = 0; kt < 16; kt++) {
        __syncthreads();  // prior O-pass done with Kt(P)/Vs
        #pragma unroll
        for (int it = 0; it < 4; it++) {
            int idx = tid + it * 256;
            int kr = idx >> 4;
            int d4 = (idx & 15) * 4;
            float4 kv = *(const float4*)(g_k + base + (size_t)(kt * 64 + kr) * Dq + d4);
            Kt[(d4 + 0) * FA_PAD + kr] = kv.x;
            Kt[(d4 + 1) * FA_PAD + kr] = kv.y;
            Kt[(d4 + 2) * FA_PAD + kr] = kv.z;
            Kt[(d4 + 3) * FA_PAD + kr] = kv.w;
            float4 vv = *(const float4*)(g_v + base + (size_t)(kt * 64 + kr) * Dq + d4);
            *(float4*)&Vs[kr * FA_PAD + d4] = vv;
        }
        __syncthreads();

        // S = (Q*scale) K^T : thread owns q rows tr*4.., k cols tc*4..
        float s_[4][4];
        #pragma unroll
        for (int i = 0; i < 4; i++)
            #pragma unroll
            for (int j = 0; j < 4; j++) s_[i][j] = 0.f;
        #pragma unroll 8
        for (int dd = 0; dd < 64; dd++) {
            const float* qp = &Qt[dd * FA_PAD + tr * 4];
            const float* kp = &Kt[dd * FA_PAD + tc * 4];
            float qv[4], kv[4];
            #pragma unroll
            for (int i = 0; i < 4; i++) qv[i] = qp[i];
            #pragma unroll
            for (int j = 0; j < 4; j++) kv[j] = kp[j];
            #pragma unroll
            for (int i = 0; i < 4; i++)
                #pragma unroll
                for (int j = 0; j < 4; j++)
                    s_[i][j] = fmaf(qv[i], kv[j], s_[i][j]);
        }

        // online softmax per q row (16 tc lanes hold the row)
        #pragma unroll
        for (int i = 0; i < 4; i++) {
            float mx = fmaxf(fmaxf(s_[i][0], s_[i][1]), fmaxf(s_[i][2], s_[i][3]));
            #pragma unroll
            for (int o = 8; o; o >>= 1) mx = fmaxf(mx, __shfl_xor_sync(0xffffffffu, mx, o));
            float mnew = fmaxf(m_i[i], mx);
            float corr = __expf(m_i[i] - mnew);
            float rs = 0.f;
            #pragma unroll
            for (int j = 0; j < 4; j++) {
                s_[i][j] = __expf(s_[i][j] - mnew);
                rs += s_[i][j];
            }
            #pragma unroll
            for (int o = 8; o; o >>= 1) rs += __shfl_xor_sync(0xffffffffu, rs, o);
            l_i[i] = l_i[i] * corr + rs;
            m_i[i] = mnew;
            #pragma unroll
            for (int j = 0; j < 4; j++) o_[i][j] *= corr;
        }
        __syncthreads();  // everyone done reading Kt

        // write P transposed into Kt buffer: Pt[k][q]
        float* Pt = Kt;
        #pragma unroll
        for (int j = 0; j < 4; j++) {
            float4 p4 = make_float4(s_[0][j], s_[1][j], s_[2][j], s_[3][j]);
            *(float4*)&Pt[(tc * 4 + j) * FA_PAD + tr * 4] = p4;
        }
        __syncthreads();

        // O += P V : thread owns q rows tr*4.., d cols tc*4..
        #pragma unroll 8
        for (int kk = 0; kk < 64; kk++) {
            const float* pp = &Pt[kk * FA_PAD + tr * 4];
            const float* vp = &Vs[kk * FA_PAD + tc * 4];
            float pv[4], vv[4];
            #pragma unroll
            for (int i = 0; i < 4; i++) pv[i] = pp[i];
            #pragma unroll
            for (int j = 0; j < 4; j++) vv[j] = vp[j];
            #pragma unroll
            for (int i = 0; i < 4; i++)
                #pragma unroll
                for (int j = 0; j < 4; j++)
                    o_[i][j] = fmaf(pv[i], vv[j], o_[i][j]);
        }
    }

    // epilogue: x2 = x1 + O/l
    #pragma unroll
    for (int i = 0; i < 4; i++) {
        float inv = 1.0f / l_i[i];
        size_t row = (size_t)(b * Tq + qblk * 64 + tr * 4 + i);
        const float* xr = g_x1 + row * Dq + h * HD + tc * 4;
        float4 r = *(const float4*)xr;
        float4 o4 = make_float4(r.x + o_[i][0] * inv, r.y + o_[i][1] * inv,
                                r.z + o_[i][2] * inv, r.w + o_[i][3] * inv);
        *(float4*)(g_x2 + row * Dq + h * HD + tc * 4) = o4;
    }
}

// ---------------- launch ----------------
extern "C" void kernel_launch(void* const* d_in, const int* in_sizes, int n_in,
                              void* d_out, int out_size) {
    const float* x     = (const float*)d_in[0];
    const float* wq    = (const float*)d_in[1];
    const float* wk    = (const float*)d_in[2];
    const float* wv    = (const float*)d_in[3];
    const float* ln1_g = (const float*)d_in[4];
    const float* ln1_b = (const float*)d_in[5];
    const float* se_w1 = (const float*)d_in[6];
    const float* se_w2 = (const float*)d_in[7];
    const float* ffn_g = (const float*)d_in[8];
    const float* ffn_b = (const float*)d_in[9];
    const float* w1    = (const float*)d_in[10];
    const float* b1    = (const float*)d_in[11];
    const float* w2    = (const float*)d_in[12];
    const float* b2    = (const float*)d_in[13];
    float* out = (float*)d_out;

    float *pn = 0, *pq = 0, *pk = 0, *pv = 0, *pn2 = 0, *ph = 0, *px2 = 0;
    cudaGetSymbolAddress((void**)&pn,  g_n);
    cudaGetSymbolAddress((void**)&pq,  g_q);
    cudaGetSymbolAddress((void**)&pk,  g_k);
    cudaGetSymbolAddress((void**)&pv,  g_v);
    cudaGetSymbolAddress((void**)&pn2, g_n2);
    cudaGetSymbolAddress((void**)&ph,  g_h);
    cudaGetSymbolAddress((void**)&px2, g_x2);

    // SE gate
    row_mean_kernel<<<NTOK / 8, 256>>>(x);
    se1_kernel<<<Bq, 256>>>(se_w1);
    se2_kernel<<<Bq, 1024>>>(se_w2);
    se_ln1_kernel<<<NTOK, 128>>>(x, ln1_g, ln1_b);

    // QKV projections
    dim3 gq(Dq / 128, NTOK / 128);
    sgemm_kernel<0><<<gq, 256>>>(pn, wq, pq, NTOK, Dq, Dq, nullptr, nullptr);
    sgemm_kernel<0><<<gq, 256>>>(pn, wk, pk, NTOK, Dq, Dq, nullptr, nullptr);
    sgemm_kernel<0><<<gq, 256>>>(pn, wv, pv, NTOK, Dq, Dq, nullptr, nullptr);

    // attention (writes x2 = x1 + attn)
    cudaFuncSetAttribute(flash_kernel, cudaFuncAttributeMaxDynamicSharedMemorySize, FA_SMEM);
    flash_kernel<<<dim3(Tq / 64, Hq, Bq), 256, FA_SMEM>>>();

    // FFN
    ln2_kernel<<<NTOK, 128>>>(ffn_g, ffn_b);
    sgemm_kernel<1><<<dim3(FFN / 128, NTOK / 128), 256>>>(pn2, w1, ph, NTOK, FFN, Dq, b1, nullptr);
    sgemm_kernel<2><<<dim3(Dq / 128, NTOK / 128), 256>>>(ph, w2, out, NTOK, Dq, FFN, b2, px2);
}

// round 6
// speedup vs baseline: 1.8975x; 1.8975x over previous
#include <cuda_runtime.h>
#include <math.h>
#include <stdint.h>

#define Bq 16
#define Tq 1024
#define Dq 512
#define Hq 8
#define HD 64
#define FFN 2048
#define SEH 256
#define NTOK (Bq*Tq)   // 16384

// ---------------- scratch (device globals; no allocs allowed) ----------------
__device__ float g_y[NTOK];              // row means (B,T)
__device__ float g_z[Bq*SEH];            // relu(y@se_w1)
__device__ float g_gate[NTOK];           // sigmoid gate
__device__ float g_x1[(size_t)NTOK*Dq];  // x after SE gate
__device__ float g_n[(size_t)NTOK*Dq];   // LN1 out
__device__ float g_q[(size_t)NTOK*Dq];
__device__ float g_k[(size_t)NTOK*Dq];
__device__ float g_v[(size_t)NTOK*Dq];
__device__ float g_x2[(size_t)NTOK*Dq];  // x1 + attn
__device__ float g_n2[(size_t)NTOK*Dq];  // LN2 out
__device__ float g_h[(size_t)NTOK*FFN];  // gelu(ffn1)

// ---------------- helpers ----------------
__device__ __forceinline__ float ftf(float x) {
    uint32_t u;
    asm("cvt.rna.tf32.f32 %0, %1;" : "=r"(u) : "f"(x));
    return __uint_as_float(u);
}

__device__ __forceinline__ void mma_tf32(float* c, const float* a, const float* b) {
    const uint32_t* A = reinterpret_cast<const uint32_t*>(a);
    const uint32_t* B = reinterpret_cast<const uint32_t*>(b);
    asm volatile(
        "mma.sync.aligned.m16n8k8.row.col.f32.tf32.tf32.f32 "
        "{%0,%1,%2,%3}, {%4,%5,%6,%7}, {%8,%9}, {%0,%1,%2,%3};"
        : "+f"(c[0]), "+f"(c[1]), "+f"(c[2]), "+f"(c[3])
        : "r"(A[0]), "r"(A[1]), "r"(A[2]), "r"(A[3]), "r"(B[0]), "r"(B[1]));
}

// ---------------- SE: row mean over D ----------------
__global__ void row_mean_kernel(const float* __restrict__ x) {
    int warp = blockIdx.x * (blockDim.x >> 5) + (threadIdx.x >> 5);
    int lane = threadIdx.x & 31;
    if (warp >= NTOK) return;
    const float4* row = (const float4*)(x + (size_t)warp * Dq);
    float s = 0.f;
    #pragma unroll
    for (int it = 0; it < 4; it++) {
        float4 v = row[lane + it * 32];
        s += v.x + v.y + v.z + v.w;
    }
    #pragma unroll
    for (int o = 16; o; o >>= 1) s += __shfl_xor_sync(0xffffffffu, s, o);
    if (lane == 0) g_y[warp] = s * (1.0f / Dq);
}

// z = relu(y @ se_w1) : (16,1024)@(1024,256)
__global__ void se1_kernel(const float* __restrict__ se_w1) {
    __shared__ float ys[Tq];
    int b = blockIdx.x;
    for (int i = threadIdx.x; i < Tq; i += 256) ys[i] = g_y[b * Tq + i];
    __syncthreads();
    int j = threadIdx.x;  // 256 threads
    float acc = 0.f;
    #pragma unroll 8
    for (int t = 0; t < Tq; t++) acc = fmaf(ys[t], se_w1[t * SEH + j], acc);
    g_z[b * SEH + j] = fmaxf(acc, 0.f);
}

// gate = sigmoid(z @ se_w2) : (16,256)@(256,1024)
__global__ void se2_kernel(const float* __restrict__ se_w2) {
    __shared__ float zs[SEH];
    int b = blockIdx.x;
    if (threadIdx.x < SEH) zs[threadIdx.x] = g_z[b * SEH + threadIdx.x];
    __syncthreads();
    int t = threadIdx.x;  // 1024 threads
    float acc = 0.f;
    #pragma unroll 8
    for (int j = 0; j < SEH; j++) acc = fmaf(zs[j], se_w2[j * Tq + t], acc);
    g_gate[b * Tq + t] = 1.0f / (1.0f + expf(-acc));
}

// ---------------- block reduce (128 threads) ----------------
__device__ __forceinline__ float block_reduce_sum128(float v, float* red) {
    #pragma unroll
    for (int o = 16; o; o >>= 1) v += __shfl_xor_sync(0xffffffffu, v, o);
    int w = threadIdx.x >> 5;
    if ((threadIdx.x & 31) == 0) red[w] = v;
    __syncthreads();
    float r = red[0] + red[1] + red[2] + red[3];
    __syncthreads();
    return r;
}

// x1 = x*(1+gate); n = LN(x1)*g + b     (one block per token row, 128 thr)
__global__ void se_ln1_kernel(const float* __restrict__ x,
                              const float* __restrict__ gam,
                              const float* __restrict__ bet) {
    __shared__ float red[4];
    int row = blockIdx.x;
    float gm = 1.0f + g_gate[row];
    float4 v = ((const float4*)(x + (size_t)row * Dq))[threadIdx.x];
    v.x *= gm; v.y *= gm; v.z *= gm; v.w *= gm;
    ((float4*)(g_x1 + (size_t)row * Dq))[threadIdx.x] = v;
    float s = block_reduce_sum128(v.x + v.y + v.z + v.w, red);
    float mu = s * (1.0f / Dq);
    float d0 = v.x - mu, d1 = v.y - mu, d2 = v.z - mu, d3 = v.w - mu;
    float ss = block_reduce_sum128(d0*d0 + d1*d1 + d2*d2 + d3*d3, red);
    float rstd = rsqrtf(ss * (1.0f / Dq) + 1e-5f);
    float4 gg = ((const float4*)gam)[threadIdx.x];
    float4 bb = ((const float4*)bet)[threadIdx.x];
    float4 o = make_float4(d0*rstd*gg.x + bb.x, d1*rstd*gg.y + bb.y,
                           d2*rstd*gg.z + bb.z, d3*rstd*gg.w + bb.w);
    ((float4*)(g_n + (size_t)row * Dq))[threadIdx.x] = o;
}

// n2 = LN(x2)*g + b
__global__ void ln2_kernel(const float* __restrict__ gam,
                           const float* __restrict__ bet) {
    __shared__ float red[4];
    int row = blockIdx.x;
    float4 v = ((const float4*)(g_x2 + (size_t)row * Dq))[threadIdx.x];
    float s = block_reduce_sum128(v.x + v.y + v.z + v.w, red);
    float mu = s * (1.0f / Dq);
    float d0 = v.x - mu, d1 = v.y - mu, d2 = v.z - mu, d3 = v.w - mu;
    float ss = block_reduce_sum128(d0*d0 + d1*d1 + d2*d2 + d3*d3, red);
    float rstd = rsqrtf(ss * (1.0f / Dq) + 1e-5f);
    float4 gg = ((const float4*)gam)[threadIdx.x];
    float4 bb = ((const float4*)bet)[threadIdx.x];
    float4 o = make_float4(d0*rstd*gg.x + bb.x, d1*rstd*gg.y + bb.y,
                           d2*rstd*gg.z + bb.z, d3*rstd*gg.w + bb.w);
    ((float4*)(g_n2 + (size_t)row * Dq))[threadIdx.x] = o;
}

// ---------------- tf32 tensor-core GEMM 128x128x32, 256 thr ----------------
// 8 warps: warp (wm,wn) owns 64x32, as 4x4 grid of m16n8k8 mma tiles.
// MODE 0: C = A@B    MODE 1: C = gelu(A@B + bias)    MODE 2: C = resid + A@B + bias
#define AS_STRIDE 36    // 36 mod 32 = 4  -> a-frag LDS bank = 4g + t (conflict-free)
#define BS_STRIDE 136   // 136 mod 32 = 8 -> b-frag LDS bank = 8t + g (conflict-free)

template <int MODE>
__device__ __forceinline__
void gemm_tf32_body(const float* __restrict__ A, const float* __restrict__ B,
                    float* __restrict__ C, int N, int K, int brow, int bcol,
                    const float* __restrict__ bias, const float* __restrict__ resid) {
    __shared__ __align__(16) float As[128][AS_STRIDE];  // [m][k]
    __shared__ __align__(16) float Bs[32][BS_STRIDE];   // [k][n]

    const int tid  = threadIdx.x;
    const int lane = tid & 31;
    const int warp = tid >> 5;
    const int wm = warp >> 2;          // 0..1  (64-row slab)
    const int wn = warp & 3;           // 0..3  (32-col slab)
    const int g  = lane >> 2;          // 0..7
    const int t  = lane & 3;           // 0..3

    float acc[4][4][4];
    #pragma unroll
    for (int mt = 0; mt < 4; mt++)
        #pragma unroll
        for (int nt = 0; nt < 4; nt++)
            #pragma unroll
            for (int e = 0; e < 4; e++) acc[mt][nt][e] = 0.f;

    for (int k0 = 0; k0 < K; k0 += 32) {
        // stage A tile (128x32) with tf32 rounding
        #pragma unroll
        for (int it = 0; it < 4; it++) {
            int i = tid + it * 256;        // float4 index 0..1023
            int row = i >> 3;
            int kc = (i & 7) * 4;
            float4 v = *(const float4*)(A + (size_t)(brow + row) * K + k0 + kc);
            v.x = ftf(v.x); v.y = ftf(v.y); v.z = ftf(v.z); v.w = ftf(v.w);
            *(float4*)&As[row][kc] = v;
        }
        // stage B tile (32x128) with tf32 rounding
        #pragma unroll
        for (int it = 0; it < 4; it++) {
            int i = tid + it * 256;
            int row = i >> 5;
            int col = (i & 31) * 4;
            float4 v = *(const float4*)(B + (size_t)(k0 + row) * N + bcol + col);
            v.x = ftf(v.x); v.y = ftf(v.y); v.z = ftf(v.z); v.w = ftf(v.w);
            *(float4*)&Bs[row][col] = v;
        }
        __syncthreads();

        #pragma unroll
        for (int ks = 0; ks < 4; ks++) {
            const int kk = ks * 8;
            float a[4][4], b[4][2];
            #pragma unroll
            for (int mt = 0; mt < 4; mt++) {
                int mrow = wm * 64 + mt * 16 + g;
                a[mt][0] = As[mrow][kk + t];
                a[mt][1] = As[mrow + 8][kk + t];
                a[mt][2] = As[mrow][kk + t + 4];
                a[mt][3] = As[mrow + 8][kk + t + 4];
            }
            #pragma unroll
            for (int nt = 0; nt < 4; nt++) {
                int ncol = wn * 32 + nt * 8 + g;
                b[nt][0] = Bs[kk + t][ncol];
                b[nt][1] = Bs[kk + t + 4][ncol];
            }
            #pragma unroll
            for (int mt = 0; mt < 4; mt++)
                #pragma unroll
                for (int nt = 0; nt < 4; nt++)
                    mma_tf32(acc[mt][nt], a[mt], b[nt]);
        }
        __syncthreads();
    }

    // epilogue: c0 (g, 2t), c1 (g, 2t+1), c2 (g+8, 2t), c3 (g+8, 2t+1)
    #pragma unroll
    for (int mt = 0; mt < 4; mt++) {
        #pragma unroll
        for (int nt = 0; nt < 4; nt++) {
            int gr = brow + wm * 64 + mt * 16 + g;
            int gc = bcol + wn * 32 + nt * 8 + 2 * t;
            #pragma unroll
            for (int half = 0; half < 2; half++) {
                size_t row = (size_t)(gr + half * 8);
                float v0 = acc[mt][nt][half * 2 + 0];
                float v1 = acc[mt][nt][half * 2 + 1];
                if (MODE == 1) {
                    float u0 = v0 + bias[gc], u1 = v1 + bias[gc + 1];
                    v0 = 0.5f * u0 * (1.0f + erff(u0 * 0.70710678118654752f));
                    v1 = 0.5f * u1 * (1.0f + erff(u1 * 0.70710678118654752f));
                } else if (MODE == 2) {
                    v0 = v0 + bias[gc] + resid[row * N + gc];
                    v1 = v1 + bias[gc + 1] + resid[row * N + gc + 1];
                }
                *(float2*)&C[row * N + gc] = make_float2(v0, v1);
            }
        }
    }
}

template <int MODE>
__global__ __launch_bounds__(256)
void gemm_tf32_kernel(const float* __restrict__ A, const float* __restrict__ B,
                      float* __restrict__ C, int M, int N, int K,
                      const float* __restrict__ bias, const float* __restrict__ resid) {
    gemm_tf32_body<MODE>(A, B, C, N, K, blockIdx.y * 128, blockIdx.x * 128, bias, resid);
}

// Fused QKV: grid.x = 12 (3 weights x 4 col-blocks). One read pass over A.
__global__ __launch_bounds__(256)
void gemm_qkv_kernel(const float* __restrict__ A,
                     const float* __restrict__ wq, const float* __restrict__ wk,
                     const float* __restrict__ wv,
                     float* __restrict__ oq, float* __restrict__ ok,
                     float* __restrict__ ov) {
    int which = blockIdx.x >> 2;          // 0=q 1=k 2=v
    int bcol = (blockIdx.x & 3) * 128;
    const float* B = which == 0 ? wq : (which == 1 ? wk : wv);
    float* C = which == 0 ? oq : (which == 1 ? ok : ov);
    gemm_tf32_body<0>(A, B, C, Dq, Dq, blockIdx.y * 128, bcol, nullptr, nullptr);
}

// ---------------- flash attention: 64q x 64k tiles, head dim 64 ----------------
// grid (T/64, H, B), 256 threads. x2 = x1 + softmax(QK^T/sqrt(d)) V
#define FA_PAD 68
#define FA_SMEM (3 * 64 * FA_PAD * 4)
__global__ __launch_bounds__(256)
void flash_kernel() {
    extern __shared__ float sm[];
    float* Qt = sm;                  // [dd][q]   64 x 68
    float* Kt = sm + 64 * FA_PAD;    // [dd][k] ; reused as Pt[k][q]
    float* Vs = Kt + 64 * FA_PAD;    // [key][dd]

    const int tid = threadIdx.x;
    const int qblk = blockIdx.x;
    const int h = blockIdx.y;
    const int b = blockIdx.z;
    const int tr = tid >> 4;   // q group 0..15
    const int tc = tid & 15;   // col group 0..15
    const size_t base = ((size_t)b * Tq) * Dq + h * HD;
    const float scale = 0.125f;  // 1/sqrt(64)

    #pragma unroll
    for (int it = 0; it < 4; it++) {
        int idx = tid + it * 256;
        int qr = idx >> 4;
        int d4 = (idx & 15) * 4;
        float4 v = *(const float4*)(g_q + base + (size_t)(qblk * 64 + qr) * Dq + d4);
        Qt[(d4 + 0) * FA_PAD + qr] = v.x * scale;
        Qt[(d4 + 1) * FA_PAD + qr] = v.y * scale;
        Qt[(d4 + 2) * FA_PAD + qr] = v.z * scale;
        Qt[(d4 + 3) * FA_PAD + qr] = v.w * scale;
    }

    float m_i[4], l_i[4], o_[4][4];
    #pragma unroll
    for (int i = 0; i < 4; i++) {
        m_i[i] = -INFINITY; l_i[i] = 0.f;
        #pragma unroll
        for (int j = 0; j < 4; j++) o_[i][j] = 0.f;
    }

    for (int kt = 0; kt < 16; kt++) {
        __syncthreads();
        #pragma unroll
        for (int it = 0; it < 4; it++) {
            int idx = tid + it * 256;
            int kr = idx >> 4;
            int d4 = (idx & 15) * 4;
            float4 kv = *(const float4*)(g_k + base + (size_t)(kt * 64 + kr) * Dq + d4);
            Kt[(d4 + 0) * FA_PAD + kr] = kv.x;
            Kt[(d4 + 1) * FA_PAD + kr] = kv.y;
            Kt[(d4 + 2) * FA_PAD + kr] = kv.z;
            Kt[(d4 + 3) * FA_PAD + kr] = kv.w;
            float4 vv = *(const float4*)(g_v + base + (size_t)(kt * 64 + kr) * Dq + d4);
            *(float4*)&Vs[kr * FA_PAD + d4] = vv;
        }
        __syncthreads();

        float s_[4][4];
        #pragma unroll
        for (int i = 0; i < 4; i++)
            #pragma unroll
            for (int j = 0; j < 4; j++) s_[i][j] = 0.f;
        #pragma unroll 8
        for (int dd = 0; dd < 64; dd++) {
            const float* qp = &Qt[dd * FA_PAD + tr * 4];
            const float* kp = &Kt[dd * FA_PAD + tc * 4];
            float qv[4], kv[4];
            #pragma unroll
            for (int i = 0; i < 4; i++) qv[i] = qp[i];
            #pragma unroll
            for (int j = 0; j < 4; j++) kv[j] = kp[j];
            #pragma unroll
            for (int i = 0; i < 4; i++)
                #pragma unroll
                for (int j = 0; j < 4; j++)
                    s_[i][j] = fmaf(qv[i], kv[j], s_[i][j]);
        }

        #pragma unroll
        for (int i = 0; i < 4; i++) {
            float mx = fmaxf(fmaxf(s_[i][0], s_[i][1]), fmaxf(s_[i][2], s_[i][3]));
            #pragma unroll
            for (int o = 8; o; o >>= 1) mx = fmaxf(mx, __shfl_xor_sync(0xffffffffu, mx, o));
            float mnew = fmaxf(m_i[i], mx);
            float corr = __expf(m_i[i] - mnew);
            float rs = 0.f;
            #pragma unroll
            for (int j = 0; j < 4; j++) {
                s_[i][j] = __expf(s_[i][j] - mnew);
                rs += s_[i][j];
            }
            #pragma unroll
            for (int o = 8; o; o >>= 1) rs += __shfl_xor_sync(0xffffffffu, rs, o);
            l_i[i] = l_i[i] * corr + rs;
            m_i[i] = mnew;
            #pragma unroll
            for (int j = 0; j < 4; j++) o_[i][j] *= corr;
        }
        __syncthreads();

        float* Pt = Kt;
        #pragma unroll
        for (int j = 0; j < 4; j++) {
            float4 p4 = make_float4(s_[0][j], s_[1][j], s_[2][j], s_[3][j]);
            *(float4*)&Pt[(tc * 4 + j) * FA_PAD + tr * 4] = p4;
        }
        __syncthreads();

        #pragma unroll 8
        for (int kk = 0; kk < 64; kk++) {
            const float* pp = &Pt[kk * FA_PAD + tr * 4];
            const float* vp = &Vs[kk * FA_PAD + tc * 4];
            float pv[4], vv[4];
            #pragma unroll
            for (int i = 0; i < 4; i++) pv[i] = pp[i];
            #pragma unroll
            for (int j = 0; j < 4; j++) vv[j] = vp[j];
            #pragma unroll
            for (int i = 0; i < 4; i++)
                #pragma unroll
                for (int j = 0; j < 4; j++)
                    o_[i][j] = fmaf(pv[i], vv[j], o_[i][j]);
        }
    }

    #pragma unroll
    for (int i = 0; i < 4; i++) {
        float inv = 1.0f / l_i[i];
        size_t row = (size_t)(b * Tq + qblk * 64 + tr * 4 + i);
        const float* xr = g_x1 + row * Dq + h * HD + tc * 4;
        float4 r = *(const float4*)xr;
        float4 o4 = make_float4(r.x + o_[i][0] * inv, r.y + o_[i][1] * inv,
                                r.z + o_[i][2] * inv, r.w + o_[i][3] * inv);
        *(float4*)(g_x2 + row * Dq + h * HD + tc * 4) = o4;
    }
}

// ---------------- launch ----------------
extern "C" void kernel_launch(void* const* d_in, const int* in_sizes, int n_in,
                              void* d_out, int out_size) {
    const float* x     = (const float*)d_in[0];
    const float* wq    = (const float*)d_in[1];
    const float* wk    = (const float*)d_in[2];
    const float* wv    = (const float*)d_in[3];
    const float* ln1_g = (const float*)d_in[4];
    const float* ln1_b = (const float*)d_in[5];
    const float* se_w1 = (const float*)d_in[6];
    const float* se_w2 = (const float*)d_in[7];
    const float* ffn_g = (const float*)d_in[8];
    const float* ffn_b = (const float*)d_in[9];
    const float* w1    = (const float*)d_in[10];
    const float* b1    = (const float*)d_in[11];
    const float* w2    = (const float*)d_in[12];
    const float* b2    = (const float*)d_in[13];
    float* out = (float*)d_out;

    float *pn = 0, *pq = 0, *pk = 0, *pv = 0, *pn2 = 0, *ph = 0, *px2 = 0;
    cudaGetSymbolAddress((void**)&pn,  g_n);
    cudaGetSymbolAddress((void**)&pq,  g_q);
    cudaGetSymbolAddress((void**)&pk,  g_k);
    cudaGetSymbolAddress((void**)&pv,  g_v);
    cudaGetSymbolAddress((void**)&pn2, g_n2);
    cudaGetSymbolAddress((void**)&ph,  g_h);
    cudaGetSymbolAddress((void**)&px2, g_x2);

    // SE gate
    row_mean_kernel<<<NTOK / 8, 256>>>(x);
    se1_kernel<<<Bq, 256>>>(se_w1);
    se2_kernel<<<Bq, 1024>>>(se_w2);
    se_ln1_kernel<<<NTOK, 128>>>(x, ln1_g, ln1_b);

    // fused QKV projections (tf32 tensor cores, one launch)
    gemm_qkv_kernel<<<dim3(12, NTOK / 128), 256>>>(pn, wq, wk, wv, pq, pk, pv);

    // attention (writes x2 = x1 + attn)
    cudaFuncSetAttribute(flash_kernel, cudaFuncAttributeMaxDynamicSharedMemorySize, FA_SMEM);
    flash_kernel<<<dim3(Tq / 64, Hq, Bq), 256, FA_SMEM>>>();

    // FFN (tf32 tensor cores)
    ln2_kernel<<<NTOK, 128>>>(ffn_g, ffn_b);
    gemm_tf32_kernel<1><<<dim3(FFN / 128, NTOK / 128), 256>>>(pn2, w1, ph, NTOK, FFN, Dq, b1, nullptr);
    gemm_tf32_kernel<2><<<dim3(Dq / 128, NTOK / 128), 256>>>(ph, w2, out, NTOK, Dq, FFN, b2, px2);
}

// round 9
// speedup vs baseline: 2.7389x; 1.4435x over previous
#include <cuda_runtime.h>
#include <math.h>
#include <stdint.h>

#define Bq 16
#define Tq 1024
#define Dq 512
#define Hq 8
#define HD 64
#define FFN 2048
#define SEH 256
#define NTOK (Bq*Tq)   // 16384

// ---------------- scratch (device globals; no allocs allowed) ----------------
__device__ float g_y[NTOK];              // row means (B,T)
__device__ float g_z[Bq*SEH];            // relu(y@se_w1)
__device__ float g_gate[NTOK];           // sigmoid gate
__device__ float g_x1[(size_t)NTOK*Dq];  // x after SE gate
__device__ float g_n[(size_t)NTOK*Dq];   // LN1 out
__device__ float g_q[(size_t)NTOK*Dq];
__device__ float g_k[(size_t)NTOK*Dq];
__device__ float g_v[(size_t)NTOK*Dq];
__device__ float g_x2[(size_t)NTOK*Dq];  // x1 + attn
__device__ float g_n2[(size_t)NTOK*Dq];  // LN2 out
__device__ float g_h[(size_t)NTOK*FFN];  // gelu(ffn1)

// ---------------- helpers ----------------
__device__ __forceinline__ float ftf(float x) {
    uint32_t u;
    asm("cvt.rna.tf32.f32 %0, %1;" : "=r"(u) : "f"(x));
    return __uint_as_float(u);
}

__device__ __forceinline__ void mma_tf32(float* c, const float* a, const float* b) {
    const uint32_t* A = reinterpret_cast<const uint32_t*>(a);
    const uint32_t* B = reinterpret_cast<const uint32_t*>(b);
    asm volatile(
        "mma.sync.aligned.m16n8k8.row.col.f32.tf32.tf32.f32 "
        "{%0,%1,%2,%3}, {%4,%5,%6,%7}, {%8,%9}, {%0,%1,%2,%3};"
        : "+f"(c[0]), "+f"(c[1]), "+f"(c[2]), "+f"(c[3])
        : "r"(A[0]), "r"(A[1]), "r"(A[2]), "r"(A[3]), "r"(B[0]), "r"(B[1]));
}

// ---------------- SE: row mean over D ----------------
__global__ void row_mean_kernel(const float* __restrict__ x) {
    int warp = blockIdx.x * (blockDim.x >> 5) + (threadIdx.x >> 5);
    int lane = threadIdx.x & 31;
    if (warp >= NTOK) return;
    const float4* row = (const float4*)(x + (size_t)warp * Dq);
    float s = 0.f;
    #pragma unroll
    for (int it = 0; it < 4; it++) {
        float4 v = row[lane + it * 32];
        s += v.x + v.y + v.z + v.w;
    }
    #pragma unroll
    for (int o = 16; o; o >>= 1) s += __shfl_xor_sync(0xffffffffu, s, o);
    if (lane == 0) g_y[warp] = s * (1.0f / Dq);
}

// z = relu(y @ se_w1) : (16,1024)@(1024,256)
__global__ void se1_kernel(const float* __restrict__ se_w1) {
    __shared__ float ys[Tq];
    int b = blockIdx.x;
    for (int i = threadIdx.x; i < Tq; i += 256) ys[i] = g_y[b * Tq + i];
    __syncthreads();
    int j = threadIdx.x;  // 256 threads
    float acc = 0.f;
    #pragma unroll 8
    for (int t = 0; t < Tq; t++) acc = fmaf(ys[t], se_w1[t * SEH + j], acc);
    g_z[b * SEH + j] = fmaxf(acc, 0.f);
}

// gate = sigmoid(z @ se_w2) : (16,256)@(256,1024)
__global__ void se2_kernel(const float* __restrict__ se_w2) {
    __shared__ float zs[SEH];
    int b = blockIdx.x;
    if (threadIdx.x < SEH) zs[threadIdx.x] = g_z[b * SEH + threadIdx.x];
    __syncthreads();
    int t = threadIdx.x;  // 1024 threads
    float acc = 0.f;
    #pragma unroll 8
    for (int j = 0; j < SEH; j++) acc = fmaf(zs[j], se_w2[j * Tq + t], acc);
    g_gate[b * Tq + t] = 1.0f / (1.0f + expf(-acc));
}

// ---------------- block reduce (128 threads) ----------------
__device__ __forceinline__ float block_reduce_sum128(float v, float* red) {
    #pragma unroll
    for (int o = 16; o; o >>= 1) v += __shfl_xor_sync(0xffffffffu, v, o);
    int w = threadIdx.x >> 5;
    if ((threadIdx.x & 31) == 0) red[w] = v;
    __syncthreads();
    float r = red[0] + red[1] + red[2] + red[3];
    __syncthreads();
    return r;
}

// x1 = x*(1+gate); n = LN(x1)*g + b     (one block per token row, 128 thr)
__global__ void se_ln1_kernel(const float* __restrict__ x,
                              const float* __restrict__ gam,
                              const float* __restrict__ bet) {
    __shared__ float red[4];
    int row = blockIdx.x;
    float gm = 1.0f + g_gate[row];
    float4 v = ((const float4*)(x + (size_t)row * Dq))[threadIdx.x];
    v.x *= gm; v.y *= gm; v.z *= gm; v.w *= gm;
    ((float4*)(g_x1 + (size_t)row * Dq))[threadIdx.x] = v;
    float s = block_reduce_sum128(v.x + v.y + v.z + v.w, red);
    float mu = s * (1.0f / Dq);
    float d0 = v.x - mu, d1 = v.y - mu, d2 = v.z - mu, d3 = v.w - mu;
    float ss = block_reduce_sum128(d0*d0 + d1*d1 + d2*d2 + d3*d3, red);
    float rstd = rsqrtf(ss * (1.0f / Dq) + 1e-5f);
    float4 gg = ((const float4*)gam)[threadIdx.x];
    float4 bb = ((const float4*)bet)[threadIdx.x];
    float4 o = make_float4(d0*rstd*gg.x + bb.x, d1*rstd*gg.y + bb.y,
                           d2*rstd*gg.z + bb.z, d3*rstd*gg.w + bb.w);
    ((float4*)(g_n + (size_t)row * Dq))[threadIdx.x] = o;
}

// n2 = LN(x2)*g + b
__global__ void ln2_kernel(const float* __restrict__ gam,
                           const float* __restrict__ bet) {
    __shared__ float red[4];
    int row = blockIdx.x;
    float4 v = ((const float4*)(g_x2 + (size_t)row * Dq))[threadIdx.x];
    float s = block_reduce_sum128(v.x + v.y + v.z + v.w, red);
    float mu = s * (1.0f / Dq);
    float d0 = v.x - mu, d1 = v.y - mu, d2 = v.z - mu, d3 = v.w - mu;
    float ss = block_reduce_sum128(d0*d0 + d1*d1 + d2*d2 + d3*d3, red);
    float rstd = rsqrtf(ss * (1.0f / Dq) + 1e-5f);
    float4 gg = ((const float4*)gam)[threadIdx.x];
    float4 bb = ((const float4*)bet)[threadIdx.x];
    float4 o = make_float4(d0*rstd*gg.x + bb.x, d1*rstd*gg.y + bb.y,
                           d2*rstd*gg.z + bb.z, d3*rstd*gg.w + bb.w);
    ((float4*)(g_n2 + (size_t)row * Dq))[threadIdx.x] = o;
}

// ---------------- tf32 tensor-core GEMM 128x128x32, 256 thr ----------------
// 8 warps: warp (wm,wn) owns 64x32, as 4x4 grid of m16n8k8 mma tiles.
// MODE 0: C = A@B    MODE 1: C = gelu(A@B + bias)    MODE 2: C = resid + A@B + bias
#define AS_STRIDE 36    // 36 mod 32 = 4  -> a-frag LDS bank = 4g + t (conflict-free)
#define BS_STRIDE 136   // 136 mod 32 = 8 -> b-frag LDS bank = 8t + g (conflict-free)

template <int MODE>
__device__ __forceinline__
void gemm_tf32_body(const float* __restrict__ A, const float* __restrict__ B,
                    float* __restrict__ C, int N, int K, int brow, int bcol,
                    const float* __restrict__ bias, const float* __restrict__ resid) {
    __shared__ __align__(16) float As[128][AS_STRIDE];  // [m][k]
    __shared__ __align__(16) float Bs[32][BS_STRIDE];   // [k][n]

    const int tid  = threadIdx.x;
    const int lane = tid & 31;
    const int warp = tid >> 5;
    const int wm = warp >> 2;          // 0..1  (64-row slab)
    const int wn = warp & 3;           // 0..3  (32-col slab)
    const int g  = lane >> 2;          // 0..7
    const int t  = lane & 3;           // 0..3

    float acc[4][4][4];
    #pragma unroll
    for (int mt = 0; mt < 4; mt++)
        #pragma unroll
        for (int nt = 0; nt < 4; nt++)
            #pragma unroll
            for (int e = 0; e < 4; e++) acc[mt][nt][e] = 0.f;

    for (int k0 = 0; k0 < K; k0 += 32) {
        // stage A tile (128x32) with tf32 rounding
        #pragma unroll
        for (int it = 0; it < 4; it++) {
            int i = tid + it * 256;        // float4 index 0..1023
            int row = i >> 3;
            int kc = (i & 7) * 4;
            float4 v = *(const float4*)(A + (size_t)(brow + row) * K + k0 + kc);
            v.x = ftf(v.x); v.y = ftf(v.y); v.z = ftf(v.z); v.w = ftf(v.w);
            *(float4*)&As[row][kc] = v;
        }
        // stage B tile (32x128) with tf32 rounding
        #pragma unroll
        for (int it = 0; it < 4; it++) {
            int i = tid + it * 256;
            int row = i >> 5;
            int col = (i & 31) * 4;
            float4 v = *(const float4*)(B + (size_t)(k0 + row) * N + bcol + col);
            v.x = ftf(v.x); v.y = ftf(v.y); v.z = ftf(v.z); v.w = ftf(v.w);
            *(float4*)&Bs[row][col] = v;
        }
        __syncthreads();

        #pragma unroll
        for (int ks = 0; ks < 4; ks++) {
            const int kk = ks * 8;
            float a[4][4], b[4][2];
            #pragma unroll
            for (int mt = 0; mt < 4; mt++) {
                int mrow = wm * 64 + mt * 16 + g;
                a[mt][0] = As[mrow][kk + t];
                a[mt][1] = As[mrow + 8][kk + t];
                a[mt][2] = As[mrow][kk + t + 4];
                a[mt][3] = As[mrow + 8][kk + t + 4];
            }
            #pragma unroll
            for (int nt = 0; nt < 4; nt++) {
                int ncol = wn * 32 + nt * 8 + g;
                b[nt][0] = Bs[kk + t][ncol];
                b[nt][1] = Bs[kk + t + 4][ncol];
            }
            #pragma unroll
            for (int mt = 0; mt < 4; mt++)
                #pragma unroll
                for (int nt = 0; nt < 4; nt++)
                    mma_tf32(acc[mt][nt], a[mt], b[nt]);
        }
        __syncthreads();
    }

    // epilogue: c0 (g, 2t), c1 (g, 2t+1), c2 (g+8, 2t), c3 (g+8, 2t+1)
    #pragma unroll
    for (int mt = 0; mt < 4; mt++) {
        #pragma unroll
        for (int nt = 0; nt < 4; nt++) {
            int gr = brow + wm * 64 + mt * 16 + g;
            int gc = bcol + wn * 32 + nt * 8 + 2 * t;
            #pragma unroll
            for (int half = 0; half < 2; half++) {
                size_t row = (size_t)(gr + half * 8);
                float v0 = acc[mt][nt][half * 2 + 0];
                float v1 = acc[mt][nt][half * 2 + 1];
                if (MODE == 1) {
                    float u0 = v0 + bias[gc], u1 = v1 + bias[gc + 1];
                    v0 = 0.5f * u0 * (1.0f + erff(u0 * 0.70710678118654752f));
                    v1 = 0.5f * u1 * (1.0f + erff(u1 * 0.70710678118654752f));
                } else if (MODE == 2) {
                    v0 = v0 + bias[gc] + resid[row * N + gc];
                    v1 = v1 + bias[gc + 1] + resid[row * N + gc + 1];
                }
                *(float2*)&C[row * N + gc] = make_float2(v0, v1);
            }
        }
    }
}

template <int MODE>
__global__ __launch_bounds__(256)
void gemm_tf32_kernel(const float* __restrict__ A, const float* __restrict__ B,
                      float* __restrict__ C, int M, int N, int K,
                      const float* __restrict__ bias, const float* __restrict__ resid) {
    gemm_tf32_body<MODE>(A, B, C, N, K, blockIdx.y * 128, blockIdx.x * 128, bias, resid);
}

// Fused QKV: grid.x = 12 (3 weights x 4 col-blocks). One read pass over A.
__global__ __launch_bounds__(256)
void gemm_qkv_kernel(const float* __restrict__ A,
                     const float* __restrict__ wq, const float* __restrict__ wk,
                     const float* __restrict__ wv,
                     float* __restrict__ oq, float* __restrict__ ok,
                     float* __restrict__ ov) {
    int which = blockIdx.x >> 2;          // 0=q 1=k 2=v
    int bcol = (blockIdx.x & 3) * 128;
    const float* B = which == 0 ? wq : (which == 1 ? wk : wv);
    float* C = which == 0 ? oq : (which == 1 ? ok : ov);
    gemm_tf32_body<0>(A, B, C, Dq, Dq, blockIdx.y * 128, bcol, nullptr, nullptr);
}

// ---------------- tensor-core flash attention ----------------
// 128 q-rows x one (b,h) per block; 8 warps, each owns m16; 64-key tiles.
// Fragment layouts identical to the validated GEMM kernel.
#define QB 128
#define KB 64
#define KS_PAD 68   // b-frag load bank = 4g + t  (conflict-free)
#define VS_PAD 72   // b-frag load bank = 8t + g  (conflict-free)
#define PS_PAD 68   // 64 cols + pad; 68 mod 32 = 4 -> a-frag bank = 4g + t (conflict-free)
#define KS_OFF 0
#define VS_OFF (KB * KS_PAD)                 // 4352
#define PS_OFF (VS_OFF + KB * VS_PAD)        // 8960
#define FTC_SMEM ((PS_OFF + QB * PS_PAD) * 4)  // 69632+1024 -> 70656 bytes

__global__ __launch_bounds__(256)
void flash_tc_kernel() {
    extern __shared__ float sm[];
    float* Ks = sm + KS_OFF;   // [KB][KS_PAD]  (key, d)
    float* Vs = sm + VS_OFF;   // [KB][VS_PAD]  (key, d)
    float* Ps = sm + PS_OFF;   // [QB][PS_PAD]  (q, key-in-tile)

    const int tid  = threadIdx.x;
    const int lane = tid & 31;
    const int warp = tid >> 5;
    const int g = lane >> 2;   // 0..7
    const int t = lane & 3;    // 0..3
    const int qb0 = blockIdx.x * QB;
    const int h = blockIdx.y;
    const int b = blockIdx.z;
    const size_t base = ((size_t)b * Tq) * Dq + h * HD;
    const float scale = 0.125f;  // 1/sqrt(64)

    // ---- stage Q (coalesced) into smem [128][KS_PAD], then lift fragments ----
    #pragma unroll
    for (int it = 0; it < 8; it++) {
        int idx = tid + it * 256;
        int qr = idx >> 4;
        int d4 = (idx & 15) * 4;
        float4 v = *(const float4*)(g_q + base + (size_t)(qb0 + qr) * Dq + d4);
        float* dst = sm + qr * KS_PAD + d4;
        dst[0] = ftf(v.x * scale); dst[1] = ftf(v.y * scale);
        dst[2] = ftf(v.z * scale); dst[3] = ftf(v.w * scale);
    }
    __syncthreads();
    float qf[8][4];
    {
        const float* q0 = sm + (warp * 16 + g) * KS_PAD;
        const float* q8 = q0 + 8 * KS_PAD;
        #pragma unroll
        for (int ks = 0; ks < 8; ks++) {
            qf[ks][0] = q0[ks * 8 + t];
            qf[ks][1] = q8[ks * 8 + t];
            qf[ks][2] = q0[ks * 8 + t + 4];
            qf[ks][3] = q8[ks * 8 + t + 4];
        }
    }
    __syncthreads();  // staging area about to be overwritten by Ks/Vs

    float of[8][4];
    #pragma unroll
    for (int nt = 0; nt < 8; nt++)
        #pragma unroll
        for (int e = 0; e < 4; e++) of[nt][e] = 0.f;
    float m0 = -INFINITY, m1 = -INFINITY, l0 = 0.f, l1 = 0.f;

    float* prow0 = Ps + (warp * 16 + g) * PS_PAD;
    float* prow8 = prow0 + 8 * PS_PAD;

    for (int kt = 0; kt < Tq / KB; kt++) {
        // load K/V tile (64 x 64), tf32-rounded
        #pragma unroll
        for (int it = 0; it < 4; it++) {
            int idx = tid + it * 256;
            int kr = idx >> 4;
            int d4 = (idx & 15) * 4;
            float4 kv = *(const float4*)(g_k + base + (size_t)(kt * KB + kr) * Dq + d4);
            float* kd = Ks + kr * KS_PAD + d4;
            kd[0] = ftf(kv.x); kd[1] = ftf(kv.y); kd[2] = ftf(kv.z); kd[3] = ftf(kv.w);
            float4 vv = *(const float4*)(g_v + base + (size_t)(kt * KB + kr) * Dq + d4);
            float* vd = Vs + kr * VS_PAD + d4;
            vd[0] = ftf(vv.x); vd[1] = ftf(vv.y); vd[2] = ftf(vv.z); vd[3] = ftf(vv.w);
        }
        __syncthreads();

        // S = Q K^T   (B = K^T -> b0 = Ks[key=n0+g][d=kk+t])
        float s[8][4];
        #pragma unroll
        for (int nt = 0; nt < 8; nt++)
            #pragma unroll
            for (int e = 0; e < 4; e++) s[nt][e] = 0.f;
        #pragma unroll
        for (int ks = 0; ks < 8; ks++) {
            const int kk = ks * 8;
            #pragma unroll
            for (int nt = 0; nt < 8; nt++) {
                float bf[2];
                const float* kp = Ks + (nt * 8 + g) * KS_PAD + kk;
                bf[0] = kp[t];
                bf[1] = kp[t + 4];
                mma_tf32(s[nt], qf[ks], bf);
            }
        }

        // online softmax: rows g (c0,c1) and g+8 (c2,c3); quad lanes share row
        float mx0 = -INFINITY, mx1 = -INFINITY;
        #pragma unroll
        for (int nt = 0; nt < 8; nt++) {
            mx0 = fmaxf(mx0, fmaxf(s[nt][0], s[nt][1]));
            mx1 = fmaxf(mx1, fmaxf(s[nt][2], s[nt][3]));
        }
        mx0 = fmaxf(mx0, __shfl_xor_sync(0xffffffffu, mx0, 1));
        mx0 = fmaxf(mx0, __shfl_xor_sync(0xffffffffu, mx0, 2));
        mx1 = fmaxf(mx1, __shfl_xor_sync(0xffffffffu, mx1, 1));
        mx1 = fmaxf(mx1, __shfl_xor_sync(0xffffffffu, mx1, 2));
        float mn0 = fmaxf(m0, mx0), mn1 = fmaxf(m1, mx1);
        float c0 = __expf(m0 - mn0), c1 = __expf(m1 - mn1);
        float rs0 = 0.f, rs1 = 0.f;
        #pragma unroll
        for (int nt = 0; nt < 8; nt++) {
            s[nt][0] = __expf(s[nt][0] - mn0);
            s[nt][1] = __expf(s[nt][1] - mn0);
            s[nt][2] = __expf(s[nt][2] - mn1);
            s[nt][3] = __expf(s[nt][3] - mn1);
            rs0 += s[nt][0] + s[nt][1];
            rs1 += s[nt][2] + s[nt][3];
        }
        rs0 += __shfl_xor_sync(0xffffffffu, rs0, 1);
        rs0 += __shfl_xor_sync(0xffffffffu, rs0, 2);
        rs1 += __shfl_xor_sync(0xffffffffu, rs1, 1);
        rs1 += __shfl_xor_sync(0xffffffffu, rs1, 2);
        l0 = l0 * c0 + rs0;  l1 = l1 * c1 + rs1;
        m0 = mn0;            m1 = mn1;
        #pragma unroll
        for (int nt = 0; nt < 8; nt++) {
            of[nt][0] *= c0; of[nt][1] *= c0;
            of[nt][2] *= c1; of[nt][3] *= c1;
        }

        // store P to smem (tf32-rounded), c-frag layout
        #pragma unroll
        for (int nt = 0; nt < 8; nt++) {
            prow0[nt * 8 + 2 * t]     = ftf(s[nt][0]);
            prow0[nt * 8 + 2 * t + 1] = ftf(s[nt][1]);
            prow8[nt * 8 + 2 * t]     = ftf(s[nt][2]);
            prow8[nt * 8 + 2 * t + 1] = ftf(s[nt][3]);
        }
        __syncthreads();

        // O += P V   (A = P from smem, B = V: b0 = Vs[key=kk+t][d=n0+g])
        #pragma unroll
        for (int ks = 0; ks < 8; ks++) {
            const int kk = ks * 8;
            float pa[4];
            pa[0] = prow0[kk + t];
            pa[1] = prow8[kk + t];
            pa[2] = prow0[kk + t + 4];
            pa[3] = prow8[kk + t + 4];
            #pragma unroll
            for (int nt = 0; nt < 8; nt++) {
                float bf[2];
                bf[0] = Vs[(kk + t) * VS_PAD + nt * 8 + g];
                bf[1] = Vs[(kk + t + 4) * VS_PAD + nt * 8 + g];
                mma_tf32(of[nt], pa, bf);
            }
        }
        __syncthreads();  // protect Ks/Vs/Ps before next tile
    }

    // epilogue: x2 = x1 + O / l
    float inv0 = 1.0f / l0, inv1 = 1.0f / l1;
    size_t r0 = (size_t)(b * Tq + qb0 + warp * 16 + g);
    size_t r8 = r0 + 8;
    #pragma unroll
    for (int nt = 0; nt < 8; nt++) {
        int col = h * HD + nt * 8 + 2 * t;
        float2 a0 = *(const float2*)(g_x1 + r0 * Dq + col);
        float2 a8 = *(const float2*)(g_x1 + r8 * Dq + col);
        *(float2*)(g_x2 + r0 * Dq + col) =
            make_float2(a0.x + of[nt][0] * inv0, a0.y + of[nt][1] * inv0);
        *(float2*)(g_x2 + r8 * Dq + col) =
            make_float2(a8.x + of[nt][2] * inv1, a8.y + of[nt][3] * inv1);
    }
}

// ---------------- launch ----------------
extern "C" void kernel_launch(void* const* d_in, const int* in_sizes, int n_in,
                              void* d_out, int out_size) {
    const float* x     = (const float*)d_in[0];
    const float* wq    = (const float*)d_in[1];
    const float* wk    = (const float*)d_in[2];
    const float* wv    = (const float*)d_in[3];
    const float* ln1_g = (const float*)d_in[4];
    const float* ln1_b = (const float*)d_in[5];
    const float* se_w1 = (const float*)d_in[6];
    const float* se_w2 = (const float*)d_in[7];
    const float* ffn_g = (const float*)d_in[8];
    const float* ffn_b = (const float*)d_in[9];
    const float* w1    = (const float*)d_in[10];
    const float* b1    = (const float*)d_in[11];
    const float* w2    = (const float*)d_in[12];
    const float* b2    = (const float*)d_in[13];
    float* out = (float*)d_out;

    float *pn = 0, *pq = 0, *pk = 0, *pv = 0, *pn2 = 0, *ph = 0, *px2 = 0;
    cudaGetSymbolAddress((void**)&pn,  g_n);
    cudaGetSymbolAddress((void**)&pq,  g_q);
    cudaGetSymbolAddress((void**)&pk,  g_k);
    cudaGetSymbolAddress((void**)&pv,  g_v);
    cudaGetSymbolAddress((void**)&pn2, g_n2);
    cudaGetSymbolAddress((void**)&ph,  g_h);
    cudaGetSymbolAddress((void**)&px2, g_x2);

    // SE gate
    row_mean_kernel<<<NTOK / 8, 256>>>(x);
    se1_kernel<<<Bq, 256>>>(se_w1);
    se2_kernel<<<Bq, 1024>>>(se_w2);
    se_ln1_kernel<<<NTOK, 128>>>(x, ln1_g, ln1_b);

    // fused QKV projections (tf32 tensor cores, one launch)
    gemm_qkv_kernel<<<dim3(12, NTOK / 128), 256>>>(pn, wq, wk, wv, pq, pk, pv);

    // tensor-core attention (writes x2 = x1 + attn)
    cudaFuncSetAttribute(flash_tc_kernel, cudaFuncAttributeMaxDynamicSharedMemorySize, FTC_SMEM);
    flash_tc_kernel<<<dim3(Tq / QB, Hq, Bq), 256, FTC_SMEM>>>();

    // FFN (tf32 tensor cores)
    ln2_kernel<<<NTOK, 128>>>(ffn_g, ffn_b);
    gemm_tf32_kernel<1><<<dim3(FFN / 128, NTOK / 128), 256>>>(pn2, w1, ph, NTOK, FFN, Dq, b1, nullptr);
    gemm_tf32_kernel<2><<<dim3(Dq / 128, NTOK / 128), 256>>>(ph, w2, out, NTOK, Dq, FFN, b2, px2);
}

// round 11
// speedup vs baseline: 3.2580x; 1.1895x over previous
#include <cuda_runtime.h>
#include <math.h>
#include <stdint.h>

#define Bq 16
#define Tq 1024
#define Dq 512
#define Hq 8
#define HD 64
#define FFN 2048
#define SEH 256
#define NTOK (Bq*Tq)   // 16384

// ---------------- scratch (device globals; no allocs allowed) ----------------
__device__ float g_y[NTOK];              // row means (B,T)
__device__ float g_z[Bq*SEH];            // relu(y@se_w1)
__device__ float g_gate[NTOK];           // sigmoid gate
__device__ float g_x1[(size_t)NTOK*Dq];  // x after SE gate
__device__ float g_n[(size_t)NTOK*Dq];   // LN1 out
__device__ float g_q[(size_t)NTOK*Dq];
__device__ float g_k[(size_t)NTOK*Dq];
__device__ float g_v[(size_t)NTOK*Dq];
__device__ float g_x2[(size_t)NTOK*Dq];  // x1 + attn
__device__ float g_n2[(size_t)NTOK*Dq];  // LN2 out
__device__ float g_h[(size_t)NTOK*FFN];  // gelu(ffn1)

// ---------------- helpers ----------------
// mma.tf32 reads f32 regs; HW uses the tf32 bits (truncation). No explicit cvt.
__device__ __forceinline__ void mma_tf32(float* c, const float* a, const float* b) {
    const uint32_t* A = reinterpret_cast<const uint32_t*>(a);
    const uint32_t* B = reinterpret_cast<const uint32_t*>(b);
    asm volatile(
        "mma.sync.aligned.m16n8k8.row.col.f32.tf32.tf32.f32 "
        "{%0,%1,%2,%3}, {%4,%5,%6,%7}, {%8,%9}, {%0,%1,%2,%3};"
        : "+f"(c[0]), "+f"(c[1]), "+f"(c[2]), "+f"(c[3])
        : "r"(A[0]), "r"(A[1]), "r"(A[2]), "r"(A[3]), "r"(B[0]), "r"(B[1]));
}

__device__ __forceinline__ void cp_async16(float* dst, const float* src) {
    uint32_t s = (uint32_t)__cvta_generic_to_shared(dst);
    asm volatile("cp.async.cg.shared.global [%0], [%1], 16;" :: "r"(s), "l"(src));
}
#define CP_COMMIT() asm volatile("cp.async.commit_group;")
#define CP_WAIT(n)  asm volatile("cp.async.wait_group %0;" :: "n"(n))

// ---------------- SE: row mean over D ----------------
__global__ void row_mean_kernel(const float* __restrict__ x) {
    int warp = blockIdx.x * (blockDim.x >> 5) + (threadIdx.x >> 5);
    int lane = threadIdx.x & 31;
    if (warp >= NTOK) return;
    const float4* row = (const float4*)(x + (size_t)warp * Dq);
    float s = 0.f;
    #pragma unroll
    for (int it = 0; it < 4; it++) {
        float4 v = row[lane + it * 32];
        s += v.x + v.y + v.z + v.w;
    }
    #pragma unroll
    for (int o = 16; o; o >>= 1) s += __shfl_xor_sync(0xffffffffu, s, o);
    if (lane == 0) g_y[warp] = s * (1.0f / Dq);
}

// z = relu(y @ se_w1) : (16,1024)@(1024,256)
__global__ void se1_kernel(const float* __restrict__ se_w1) {
    __shared__ float ys[Tq];
    int b = blockIdx.x;
    for (int i = threadIdx.x; i < Tq; i += 256) ys[i] = g_y[b * Tq + i];
    __syncthreads();
    int j = threadIdx.x;  // 256 threads
    float acc = 0.f;
    #pragma unroll 8
    for (int t = 0; t < Tq; t++) acc = fmaf(ys[t], se_w1[t * SEH + j], acc);
    g_z[b * SEH + j] = fmaxf(acc, 0.f);
}

// gate = sigmoid(z @ se_w2) : (16,256)@(256,1024)
__global__ void se2_kernel(const float* __restrict__ se_w2) {
    __shared__ float zs[SEH];
    int b = blockIdx.x;
    if (threadIdx.x < SEH) zs[threadIdx.x] = g_z[b * SEH + threadIdx.x];
    __syncthreads();
    int t = threadIdx.x;  // 1024 threads
    float acc = 0.f;
    #pragma unroll 8
    for (int j = 0; j < SEH; j++) acc = fmaf(zs[j], se_w2[j * Tq + t], acc);
    g_gate[b * Tq + t] = 1.0f / (1.0f + expf(-acc));
}

// ---------------- block reduce (128 threads) ----------------
__device__ __forceinline__ float block_reduce_sum128(float v, float* red) {
    #pragma unroll
    for (int o = 16; o; o >>= 1) v += __shfl_xor_sync(0xffffffffu, v, o);
    int w = threadIdx.x >> 5;
    if ((threadIdx.x & 31) == 0) red[w] = v;
    __syncthreads();
    float r = red[0] + red[1] + red[2] + red[3];
    __syncthreads();
    return r;
}

// x1 = x*(1+gate); n = LN(x1)*g + b     (one block per token row, 128 thr)
__global__ void se_ln1_kernel(const float* __restrict__ x,
                              const float* __restrict__ gam,
                              const float* __restrict__ bet) {
    __shared__ float red[4];
    int row = blockIdx.x;
    float gm = 1.0f + g_gate[row];
    float4 v = ((const float4*)(x + (size_t)row * Dq))[threadIdx.x];
    v.x *= gm; v.y *= gm; v.z *= gm; v.w *= gm;
    ((float4*)(g_x1 + (size_t)row * Dq))[threadIdx.x] = v;
    float s = block_reduce_sum128(v.x + v.y + v.z + v.w, red);
    float mu = s * (1.0f / Dq);
    float d0 = v.x - mu, d1 = v.y - mu, d2 = v.z - mu, d3 = v.w - mu;
    float ss = block_reduce_sum128(d0*d0 + d1*d1 + d2*d2 + d3*d3, red);
    float rstd = rsqrtf(ss * (1.0f / Dq) + 1e-5f);
    float4 gg = ((const float4*)gam)[threadIdx.x];
    float4 bb = ((const float4*)bet)[threadIdx.x];
    float4 o = make_float4(d0*rstd*gg.x + bb.x, d1*rstd*gg.y + bb.y,
                           d2*rstd*gg.z + bb.z, d3*rstd*gg.w + bb.w);
    ((float4*)(g_n + (size_t)row * Dq))[threadIdx.x] = o;
}

// n2 = LN(x2)*g + b
__global__ void ln2_kernel(const float* __restrict__ gam,
                           const float* __restrict__ bet) {
    __shared__ float red[4];
    int row = blockIdx.x;
    float4 v = ((const float4*)(g_x2 + (size_t)row * Dq))[threadIdx.x];
    float s = block_reduce_sum128(v.x + v.y + v.z + v.w, red);
    float mu = s * (1.0f / Dq);
    float d0 = v.x - mu, d1 = v.y - mu, d2 = v.z - mu, d3 = v.w - mu;
    float ss = block_reduce_sum128(d0*d0 + d1*d1 + d2*d2 + d3*d3, red);
    float rstd = rsqrtf(ss * (1.0f / Dq) + 1e-5f);
    float4 gg = ((const float4*)gam)[threadIdx.x];
    float4 bb = ((const float4*)bet)[threadIdx.x];
    float4 o = make_float4(d0*rstd*gg.x + bb.x, d1*rstd*gg.y + bb.y,
                           d2*rstd*gg.z + bb.z, d3*rstd*gg.w + bb.w);
    ((float4*)(g_n2 + (size_t)row * Dq))[threadIdx.x] = o;
}

// ---------------- tf32 tensor-core GEMM 128x128x32, cp.async 2-stage ----------
// 8 warps: warp (wm,wn) owns 64x32, as 4x4 grid of m16n8k8 mma tiles.
// MODE 0: C = A@B    MODE 1: C = gelu(A@B + bias)    MODE 2: C = resid + A@B + bias
#define AS_STRIDE 36    // 36 mod 32 = 4  -> a-frag LDS bank = 4g + t (conflict-free)
#define BS_STRIDE 136   // 136 mod 32 = 8 -> b-frag LDS bank = 8t + g (conflict-free)
#define AS_BUF (128 * AS_STRIDE)            // 4608 floats (mod 32 == 0)
#define BS_BUF (32 * BS_STRIDE)             // 4352 floats (mod 32 == 0)
#define GEMM_SMEM ((2 * AS_BUF + 2 * BS_BUF) * 4)   // 71680 bytes

template <int MODE>
__device__ __forceinline__
void gemm_tf32_body(const float* __restrict__ A, const float* __restrict__ B,
                    float* __restrict__ C, int N, int K, int brow, int bcol,
                    const float* __restrict__ bias, const float* __restrict__ resid) {
    extern __shared__ float smx[];
    float* AsB = smx;                 // [2][128][AS_STRIDE]
    float* BsB = smx + 2 * AS_BUF;    // [2][32][BS_STRIDE]

    const int tid  = threadIdx.x;
    const int lane = tid & 31;
    const int warp = tid >> 5;
    const int wm = warp >> 2;          // 0..1  (64-row slab)
    const int wn = warp & 3;           // 0..3  (32-col slab)
    const int g  = lane >> 2;          // 0..7
    const int t  = lane & 3;           // 0..3

    float acc[4][4][4];
    #pragma unroll
    for (int mt = 0; mt < 4; mt++)
        #pragma unroll
        for (int nt = 0; nt < 4; nt++)
            #pragma unroll
            for (int e = 0; e < 4; e++) acc[mt][nt][e] = 0.f;

    auto issue = [&](int buf, int k0) {
        float* Ab = AsB + buf * AS_BUF;
        #pragma unroll
        for (int it = 0; it < 4; it++) {
            int i = tid + it * 256;
            int row = i >> 3, kc = (i & 7) * 4;
            cp_async16(Ab + row * AS_STRIDE + kc,
                       A + (size_t)(brow + row) * K + k0 + kc);
        }
        float* Bb = BsB + buf * BS_BUF;
        #pragma unroll
        for (int it = 0; it < 4; it++) {
            int i = tid + it * 256;
            int row = i >> 5, col = (i & 31) * 4;
            cp_async16(Bb + row * BS_STRIDE + col,
                       B + (size_t)(k0 + row) * N + bcol + col);
        }
    };

    issue(0, 0);
    CP_COMMIT();
    const int nk = K / 32;

    for (int ki = 0; ki < nk; ki++) {
        const int buf = ki & 1;
        CP_WAIT(0);
        __syncthreads();
        if (ki + 1 < nk) { issue(buf ^ 1, (ki + 1) * 32); CP_COMMIT(); }

        const float* Ab = AsB + buf * AS_BUF;
        const float* Bb = BsB + buf * BS_BUF;
        #pragma unroll
        for (int ks = 0; ks < 4; ks++) {
            const int kk = ks * 8;
            float a[4][4], b[4][2];
            #pragma unroll
            for (int mt = 0; mt < 4; mt++) {
                int mrow = wm * 64 + mt * 16 + g;
                a[mt][0] = Ab[mrow * AS_STRIDE + kk + t];
                a[mt][1] = Ab[(mrow + 8) * AS_STRIDE + kk + t];
                a[mt][2] = Ab[mrow * AS_STRIDE + kk + t + 4];
                a[mt][3] = Ab[(mrow + 8) * AS_STRIDE + kk + t + 4];
            }
            #pragma unroll
            for (int nt = 0; nt < 4; nt++) {
                int ncol = wn * 32 + nt * 8 + g;
                b[nt][0] = Bb[(kk + t) * BS_STRIDE + ncol];
                b[nt][1] = Bb[(kk + t + 4) * BS_STRIDE + ncol];
            }
            #pragma unroll
            for (int mt = 0; mt < 4; mt++)
                #pragma unroll
                for (int nt = 0; nt < 4; nt++)
                    mma_tf32(acc[mt][nt], a[mt], b[nt]);
        }
        // next iteration's top __syncthreads (after CP_WAIT) protects buf reuse
    }

    // epilogue: c0 (g, 2t), c1 (g, 2t+1), c2 (g+8, 2t), c3 (g+8, 2t+1)
    #pragma unroll
    for (int mt = 0; mt < 4; mt++) {
        #pragma unroll
        for (int nt = 0; nt < 4; nt++) {
            int gr = brow + wm * 64 + mt * 16 + g;
            int gc = bcol + wn * 32 + nt * 8 + 2 * t;
            #pragma unroll
            for (int half = 0; half < 2; half++) {
                size_t row = (size_t)(gr + half * 8);
                float v0 = acc[mt][nt][half * 2 + 0];
                float v1 = acc[mt][nt][half * 2 + 1];
                if (MODE == 1) {
                    float u0 = v0 + bias[gc], u1 = v1 + bias[gc + 1];
                    v0 = 0.5f * u0 * (1.0f + erff(u0 * 0.70710678118654752f));
                    v1 = 0.5f * u1 * (1.0f + erff(u1 * 0.70710678118654752f));
                } else if (MODE == 2) {
                    v0 = v0 + bias[gc] + resid[row * N + gc];
                    v1 = v1 + bias[gc + 1] + resid[row * N + gc + 1];
                }
                *(float2*)&C[row * N + gc] = make_float2(v0, v1);
            }
        }
    }
}

template <int MODE>
__global__ __launch_bounds__(256)
void gemm_tf32_kernel(const float* __restrict__ A, const float* __restrict__ B,
                      float* __restrict__ C, int M, int N, int K,
                      const float* __restrict__ bias, const float* __restrict__ resid) {
    gemm_tf32_body<MODE>(A, B, C, N, K, blockIdx.y * 128, blockIdx.x * 128, bias, resid);
}

// Fused QKV: grid.x = 12 (3 weights x 4 col-blocks). One read pass over A.
__global__ __launch_bounds__(256)
void gemm_qkv_kernel(const float* __restrict__ A,
                     const float* __restrict__ wq, const float* __restrict__ wk,
                     const float* __restrict__ wv,
                     float* __restrict__ oq, float* __restrict__ ok,
                     float* __restrict__ ov) {
    int which = blockIdx.x >> 2;          // 0=q 1=k 2=v
    int bcol = (blockIdx.x & 3) * 128;
    const float* B = which == 0 ? wq : (which == 1 ? wk : wv);
    float* C = which == 0 ? oq : (which == 1 ? ok : ov);
    gemm_tf32_body<0>(A, B, C, Dq, Dq, blockIdx.y * 128, bcol, nullptr, nullptr);
}

// ---------------- tensor-core flash attention, cp.async 2-stage K/V ----------
// 128 q-rows x one (b,h) per block; 8 warps, each owns m16; 64-key tiles.
#define QB 128
#define KB 64
#define KS_PAD 68   // b-frag load bank = 4g + t  (conflict-free)
#define VS_PAD 72   // b-frag load bank = 8t + g  (conflict-free)
#define PS_PAD 68   // a-frag load bank = 4g + t  (conflict-free)
#define KS_BUF (KB * KS_PAD)                 // 4352 floats (mod 32 == 0)
#define VS_BUF (KB * VS_PAD)                 // 4608 floats (mod 32 == 0)
#define VS_OFF (2 * KS_BUF)                  // 8704
#define PS_OFF (VS_OFF + 2 * VS_BUF)         // 17920
#define FTC_SMEM ((PS_OFF + QB * PS_PAD) * 4)  // 106496 bytes

__global__ __launch_bounds__(256)
void flash_tc_kernel() {
    extern __shared__ float sm[];
    float* Ps = sm + PS_OFF;   // [QB][PS_PAD]  (q staging, then P)

    const int tid  = threadIdx.x;
    const int lane = tid & 31;
    const int warp = tid >> 5;
    const int g = lane >> 2;   // 0..7
    const int t = lane & 3;    // 0..3
    const int qb0 = blockIdx.x * QB;
    const int h = blockIdx.y;
    const int b = blockIdx.z;
    const size_t base = ((size_t)b * Tq) * Dq + h * HD;
    const float scale = 0.125f;  // 1/sqrt(64)

    auto issue_kv = [&](int buf, int kt) {
        float* Kb = sm + buf * KS_BUF;
        float* Vb = sm + VS_OFF + buf * VS_BUF;
        #pragma unroll
        for (int it = 0; it < 4; it++) {
            int idx = tid + it * 256;
            int kr = idx >> 4;
            int d4 = (idx & 15) * 4;
            cp_async16(Kb + kr * KS_PAD + d4,
                       g_k + base + (size_t)(kt * KB + kr) * Dq + d4);
            cp_async16(Vb + kr * VS_PAD + d4,
                       g_v + base + (size_t)(kt * KB + kr) * Dq + d4);
        }
    };

    // stage Q into Ps area (group 1), prefetch KV tile 0 (group 2)
    #pragma unroll
    for (int it = 0; it < 8; it++) {
        int idx = tid + it * 256;
        int qr = idx >> 4;
        int d4 = (idx & 15) * 4;
        cp_async16(Ps + qr * PS_PAD + d4,
                   g_q + base + (size_t)(qb0 + qr) * Dq + d4);
    }
    CP_COMMIT();
    issue_kv(0, 0);
    CP_COMMIT();

    CP_WAIT(1);          // Q staged; KV0 may still be in flight
    __syncthreads();

    // lift Q fragments (warp-private rows), scale in registers
    float qf[8][4];
    {
        const float* q0 = Ps + (warp * 16 + g) * PS_PAD;
        const float* q8 = q0 + 8 * PS_PAD;
        #pragma unroll
        for (int ks = 0; ks < 8; ks++) {
            qf[ks][0] = q0[ks * 8 + t] * scale;
            qf[ks][1] = q8[ks * 8 + t] * scale;
            qf[ks][2] = q0[ks * 8 + t + 4] * scale;
            qf[ks][3] = q8[ks * 8 + t + 4] * scale;
        }
    }

    float of[8][4];
    #pragma unroll
    for (int nt = 0; nt < 8; nt++)
        #pragma unroll
        for (int e = 0; e < 4; e++) of[nt][e] = 0.f;
    float m0 = -INFINITY, m1 = -INFINITY, l0 = 0.f, l1 = 0.f;

    float* prow0 = Ps + (warp * 16 + g) * PS_PAD;
    float* prow8 = prow0 + 8 * PS_PAD;

    for (int kt = 0; kt < Tq / KB; kt++) {
        const int buf = kt & 1;
        CP_WAIT(0);
        __syncthreads();   // KV[buf] visible; prior iter's compute done
        if (kt + 1 < Tq / KB) { issue_kv(buf ^ 1, kt + 1); CP_COMMIT(); }

        const float* Kb = sm + buf * KS_BUF;
        const float* Vb = sm + VS_OFF + buf * VS_BUF;

        // S = Q K^T   (b0 = Kb[key=n0+g][d=kk+t])
        float s[8][4];
        #pragma unroll
        for (int nt = 0; nt < 8; nt++)
            #pragma unroll
            for (int e = 0; e < 4; e++) s[nt][e] = 0.f;
        #pragma unroll
        for (int ks = 0; ks < 8; ks++) {
            const int kk = ks * 8;
            #pragma unroll
            for (int nt = 0; nt < 8; nt++) {
                float bf[2];
                const float* kp = Kb + (nt * 8 + g) * KS_PAD + kk;
                bf[0] = kp[t];
                bf[1] = kp[t + 4];
                mma_tf32(s[nt], qf[ks], bf);
            }
        }

        // online softmax: rows g (c0,c1) and g+8 (c2,c3); quad lanes share row
        float mx0 = -INFINITY, mx1 = -INFINITY;
        #pragma unroll
        for (int nt = 0; nt < 8; nt++) {
            mx0 = fmaxf(mx0, fmaxf(s[nt][0], s[nt][1]));
            mx1 = fmaxf(mx1, fmaxf(s[nt][2], s[nt][3]));
        }
        mx0 = fmaxf(mx0, __shfl_xor_sync(0xffffffffu, mx0, 1));
        mx0 = fmaxf(mx0, __shfl_xor_sync(0xffffffffu, mx0, 2));
        mx1 = fmaxf(mx1, __shfl_xor_sync(0xffffffffu, mx1, 1));
        mx1 = fmaxf(mx1, __shfl_xor_sync(0xffffffffu, mx1, 2));
        float mn0 = fmaxf(m0, mx0), mn1 = fmaxf(m1, mx1);
        float c0 = __expf(m0 - mn0), c1 = __expf(m1 - mn1);
        float rs0 = 0.f, rs1 = 0.f;
        #pragma unroll
        for (int nt = 0; nt < 8; nt++) {
            s[nt][0] = __expf(s[nt][0] - mn0);
            s[nt][1] = __expf(s[nt][1] - mn0);
            s[nt][2] = __expf(s[nt][2] - mn1);
            s[nt][3] = __expf(s[nt][3] - mn1);
            rs0 += s[nt][0] + s[nt][1];
            rs1 += s[nt][2] + s[nt][3];
        }
        rs0 += __shfl_xor_sync(0xffffffffu, rs0, 1);
        rs0 += __shfl_xor_sync(0xffffffffu, rs0, 2);
        rs1 += __shfl_xor_sync(0xffffffffu, rs1, 1);
        rs1 += __shfl_xor_sync(0xffffffffu, rs1, 2);
        l0 = l0 * c0 + rs0;  l1 = l1 * c1 + rs1;
        m0 = mn0;            m1 = mn1;
        #pragma unroll
        for (int nt = 0; nt < 8; nt++) {
            of[nt][0] *= c0; of[nt][1] *= c0;
            of[nt][2] *= c1; of[nt][3] *= c1;
        }

        // store P (warp-private rows) -> only warp-level sync needed
        #pragma unroll
        for (int nt = 0; nt < 8; nt++) {
            prow0[nt * 8 + 2 * t]     = s[nt][0];
            prow0[nt * 8 + 2 * t + 1] = s[nt][1];
            prow8[nt * 8 + 2 * t]     = s[nt][2];
            prow8[nt * 8 + 2 * t + 1] = s[nt][3];
        }
        __syncwarp();

        // O += P V   (A = P from smem, B = V: b0 = Vb[key=kk+t][d=n0+g])
        #pragma unroll
        for (int ks = 0; ks < 8; ks++) {
            const int kk = ks * 8;
            float pa[4];
            pa[0] = prow0[kk + t];
            pa[1] = prow8[kk + t];
            pa[2] = prow0[kk + t + 4];
            pa[3] = prow8[kk + t + 4];
            #pragma unroll
            for (int nt = 0; nt < 8; nt++) {
                float bf[2];
                bf[0] = Vb[(kk + t) * VS_PAD + nt * 8 + g];
                bf[1] = Vb[(kk + t + 4) * VS_PAD + nt * 8 + g];
                mma_tf32(of[nt], pa, bf);
            }
        }
        // next iteration's top __syncthreads protects buffer reuse
    }

    // epilogue: x2 = x1 + O / l
    float inv0 = 1.0f / l0, inv1 = 1.0f / l1;
    size_t r0 = (size_t)(b * Tq + qb0 + warp * 16 + g);
    size_t r8 = r0 + 8;
    #pragma unroll
    for (int nt = 0; nt < 8; nt++) {
        int col = h * HD + nt * 8 + 2 * t;
        float2 a0 = *(const float2*)(g_x1 + r0 * Dq + col);
        float2 a8 = *(const float2*)(g_x1 + r8 * Dq + col);
        *(float2*)(g_x2 + r0 * Dq + col) =
            make_float2(a0.x + of[nt][0] * inv0, a0.y + of[nt][1] * inv0);
        *(float2*)(g_x2 + r8 * Dq + col) =
            make_float2(a8.x + of[nt][2] * inv1, a8.y + of[nt][3] * inv1);
    }
}

// ---------------- launch ----------------
extern "C" void kernel_launch(void* const* d_in, const int* in_sizes, int n_in,
                              void* d_out, int out_size) {
    const float* x     = (const float*)d_in[0];
    const float* wq    = (const float*)d_in[1];
    const float* wk    = (const float*)d_in[2];
    const float* wv    = (const float*)d_in[3];
    const float* ln1_g = (const float*)d_in[4];
    const float* ln1_b = (const float*)d_in[5];
    const float* se_w1 = (const float*)d_in[6];
    const float* se_w2 = (const float*)d_in[7];
    const float* ffn_g = (const float*)d_in[8];
    const float* ffn_b = (const float*)d_in[9];
    const float* w1    = (const float*)d_in[10];
    const float* b1    = (const float*)d_in[11];
    const float* w2    = (const float*)d_in[12];
    const float* b2    = (const float*)d_in[13];
    float* out = (float*)d_out;

    float *pn = 0, *pq = 0, *pk = 0, *pv = 0, *pn2 = 0, *ph = 0, *px2 = 0;
    cudaGetSymbolAddress((void**)&pn,  g_n);
    cudaGetSymbolAddress((void**)&pq,  g_q);
    cudaGetSymbolAddress((void**)&pk,  g_k);
    cudaGetSymbolAddress((void**)&pv,  g_v);
    cudaGetSymbolAddress((void**)&pn2, g_n2);
    cudaGetSymbolAddress((void**)&ph,  g_h);
    cudaGetSymbolAddress((void**)&px2, g_x2);

    cudaFuncSetAttribute(gemm_qkv_kernel,
                         cudaFuncAttributeMaxDynamicSharedMemorySize, GEMM_SMEM);
    cudaFuncSetAttribute(gemm_tf32_kernel<1>,
                         cudaFuncAttributeMaxDynamicSharedMemorySize, GEMM_SMEM);
    cudaFuncSetAttribute(gemm_tf32_kernel<2>,
                         cudaFuncAttributeMaxDynamicSharedMemorySize, GEMM_SMEM);
    cudaFuncSetAttribute(flash_tc_kernel,
                         cudaFuncAttributeMaxDynamicSharedMemorySize, FTC_SMEM);

    // SE gate
    row_mean_kernel<<<NTOK / 8, 256>>>(x);
    se1_kernel<<<Bq, 256>>>(se_w1);
    se2_kernel<<<Bq, 1024>>>(se_w2);
    se_ln1_kernel<<<NTOK, 128>>>(x, ln1_g, ln1_b);

    // fused QKV projections (tf32 tensor cores, one launch)
    gemm_qkv_kernel<<<dim3(12, NTOK / 128), 256, GEMM_SMEM>>>(pn, wq, wk, wv, pq, pk, pv);

    // tensor-core attention (writes x2 = x1 + attn)
    flash_tc_kernel<<<dim3(Tq / QB, Hq, Bq), 256, FTC_SMEM>>>();

    // FFN (tf32 tensor cores)
    ln2_kernel<<<NTOK, 128>>>(ffn_g, ffn_b);
    gemm_tf32_kernel<1><<<dim3(FFN / 128, NTOK / 128), 256, GEMM_SMEM>>>(pn2, w1, ph, NTOK, FFN, Dq, b1, nullptr);
    gemm_tf32_kernel<2><<<dim3(Dq / 128, NTOK / 128), 256, GEMM_SMEM>>>(ph, w2, out, NTOK, Dq, FFN, b2, px2);
}